// round 7
// baseline (speedup 1.0000x reference)
#include <cuda_runtime.h>
#include <math.h>

// ---------------- problem constants ----------------
#define DIMC      64
#define HW        256          // 16x16
#define BATCH     256
#define EMB_DIM   45184
#define OFF_CNNW  0
#define OFF_CNNB  36864
#define OFF_PROJW 36928
#define OFF_PROJB 45120
#define BHW       (BATCH*DIMC*HW)   // 4194304 floats = 16 MB

typedef unsigned long long ull_t;

// packed f32x2 helpers (sm_103a FFMA2 path — only reachable via PTX)
#define PACKF2(out, lo, hi) \
    asm("mov.b64 %0, {%1, %2};" : "=l"(out) : "f"(lo), "f"(hi))
#define UNPACKF2(lo, hi, in) \
    asm("mov.b64 {%0, %1}, %2;" : "=f"(lo), "=f"(hi) : "l"(in))
#define FMAF2(d, a, b, c) \
    asm("fma.rn.f32x2 %0, %1, %2, %3;" : "=l"(d) : "l"(a), "l"(b), "l"(c))

// scratch: module outputs h1,h2 and projected conv-input
__device__ float g_h1[BHW];
__device__ float g_h2[BHW];
__device__ float g_ci[BHW];

__device__ __forceinline__ void softmax_n(const float* x, float* y, int n) {
    float m = x[0];
    for (int i = 1; i < n; i++) m = fmaxf(m, x[i]);
    float s = 0.f;
    for (int i = 0; i < n; i++) { y[i] = expf(x[i] - m); s += y[i]; }
    float inv = 1.f / s;
    for (int i = 0; i < n; i++) y[i] *= inv;
}

// =====================================================================
// Kernel P: per-batch projection, f32x2 (unchanged from R4 — near floor).
// grid 256 (1 CTA/batch), 256 threads, 2 CTAs/SM, single wave.
// =====================================================================
#define P_SMEM_FLOATS (16384 + 64*68 + 64 + 16)

__global__ void __launch_bounds__(256, 2)
proj_kernel(const int* __restrict__ question,
            const float* __restrict__ img,
            const float* __restrict__ emb,
            const float* __restrict__ alpha,
            const float* __restrict__ tau0,
            const float* __restrict__ tau1,
            int mod)
{
    extern __shared__ float sm[];
    float* s_stage = sm;                   // 64*256 = 16384
    float* s_wT    = sm + 16384;           // 64*68  = 4352 (k-major, padded)
    float* s_pb    = sm + 16384 + 4352;    // 64
    float* s_scal  = s_pb + 64;            // 9 scalars

    const int b   = blockIdx.x;
    const int tid = threadIdx.x;

    if (tid == 0) {
        float tmp[4], sf[4];
        for (int t = 0; t < 3; t++) tmp[t] = alpha[mod*3 + t];
        softmax_n(tmp, sf, 3);
        s_scal[0] = sf[0]; s_scal[1] = sf[1]; s_scal[2] = sf[2];
        const int n = mod + 2;
        for (int m = 0; m < n; m++) tmp[m] = tau0[mod*4 + m];
        softmax_n(tmp, sf, n);
        s_scal[3] = sf[1];
        s_scal[4] = (n > 2) ? sf[2] : 0.f;
        s_scal[5] = (n > 3) ? sf[3] : 0.f;
        for (int m = 0; m < n; m++) tmp[m] = tau1[mod*4 + m];
        softmax_n(tmp, sf, n);
        s_scal[6] = sf[1];
        s_scal[7] = (n > 2) ? sf[2] : 0.f;
        s_scal[8] = (n > 3) ? sf[3] : 0.f;
    }
    __syncthreads();

    const float a0 = s_scal[0], a1 = s_scal[1], a2 = s_scal[2];
    const float* r0 = emb + (size_t)question[b*3 + 0] * EMB_DIM;
    const float* r1 = emb + (size_t)question[b*3 + 1] * EMB_DIM;
    const float* r2 = emb + (size_t)question[b*3 + 2] * EMB_DIM;

    if (tid < 64)
        s_pb[tid] = a0*r0[OFF_PROJB + tid] + a1*r1[OFF_PROJB + tid] + a2*r2[OFF_PROJB + tid];

    const int px = tid & 31;
    const int c0 = (tid >> 5) * 8;
    ull_t acc2[8][4];

    const float4* img4 = (const float4*)(img  + (size_t)b * DIMC * HW);
    const float4* h14  = (const float4*)(g_h1 + (size_t)b * DIMC * HW);
    const float4* h24  = (const float4*)(g_h2 + (size_t)b * DIMC * HW);
    float4* stage4 = (float4*)s_stage;

    for (int half = 0; half < 2; ++half) {
        const float w1 = s_scal[3 + 3*half + 0];
        const float w2 = s_scal[3 + 3*half + 1];
        const float w3 = s_scal[3 + 3*half + 2];

        for (int e4 = tid; e4 < 4096; e4 += 256) {
            float4 v = img4[e4];
            float4 o;
            o.x = w1*v.x; o.y = w1*v.y; o.z = w1*v.z; o.w = w1*v.w;
            if (mod >= 1) { float4 u = h14[e4]; o.x += w2*u.x; o.y += w2*u.y; o.z += w2*u.z; o.w += w2*u.w; }
            if (mod >= 2) { float4 u = h24[e4]; o.x += w3*u.x; o.y += w3*u.y; o.z += w3*u.z; o.w += w3*u.w; }
            stage4[e4] = o;
        }
        for (int e = tid; e < 4096; e += 256) {
            const int c  = e >> 6;
            const int kk = e & 63;
            const int off = OFF_PROJW + c*128 + half*64 + kk;
            s_wT[kk*68 + c] = a0*r0[off] + a1*r1[off] + a2*r2[off];
        }
        __syncthreads();

        if (half == 0) {
            #pragma unroll
            for (int ii = 0; ii < 8; ii++) {
                ull_t pbp;
                PACKF2(pbp, s_pb[c0 + ii], s_pb[c0 + ii]);
                #pragma unroll
                for (int j2 = 0; j2 < 4; j2++) acc2[ii][j2] = pbp;
            }
        }

        #pragma unroll 2
        for (int k = 0; k < 64; k++) {
            ull_t a2r[8];
            #pragma unroll
            for (int ii = 0; ii < 8; ii++) {
                const float wv = s_wT[k*68 + c0 + ii];
                PACKF2(a2r[ii], wv, wv);
            }
            ull_t b2[4];
            #pragma unroll
            for (int j2 = 0; j2 < 4; j2++)
                b2[j2] = *(const ull_t*)(s_stage + k*256 + 2*px + 64*j2);  // LDS.64, conflict-free
            #pragma unroll
            for (int j2 = 0; j2 < 4; j2++)
                #pragma unroll
                for (int ii = 0; ii < 8; ii++)
                    FMAF2(acc2[ii][j2], a2r[ii], b2[j2], acc2[ii][j2]);
        }
        __syncthreads();
    }

    float* ci = g_ci + (size_t)b * DIMC * HW;
    #pragma unroll
    for (int ii = 0; ii < 8; ii++)
        #pragma unroll
        for (int j2 = 0; j2 < 4; j2++)
            *(ull_t*)(ci + (c0 + ii)*256 + 2*px + 64*j2) = acc2[ii][j2];   // STG.64
}

// =====================================================================
// Kernel C: per-batch 3x3 conv, f32x2, oc-paired accumulators.
// grid 512 = 256 b x 2 og(32 oc), 128 threads, 4 CTAs/SM -> SINGLE WAVE.
// Pad stage TRANSPOSED [c][w][h]: strips = aligned conflict-free LDS.64.
// Weights [klocal][oc] stride 34: oc-pair via one warp-uniform LDS.64,
// zero weight packs; bv = dup-pack (alu pipe).
// =====================================================================
#define CW_STRIDE 34
#define C_SMEM_FLOATS (5184 + 144*CW_STRIDE + 32 + 8)

__global__ void __launch_bounds__(128, 4)
conv_kernel(const int* __restrict__ question,
            const float* __restrict__ emb,
            const float* __restrict__ alpha,
            float* __restrict__ out_final,
            int mod)
{
    extern __shared__ float sm[];
    float* s_pad = sm;                        // 16 * 324 (transposed [c][w18][h18])
    float* s_wc  = sm + 5184;                 // 144 * 34 = 4896
    float* s_cb  = sm + 5184 + 144*CW_STRIDE; // 32
    float* s_a   = s_cb + 32;                 // 3

    const int b   = blockIdx.x >> 1;
    const int og  = blockIdx.x & 1;
    const int tid = threadIdx.x;

    if (tid == 0) {
        float tmp[3], sf[3];
        for (int t = 0; t < 3; t++) tmp[t] = alpha[mod*3 + t];
        softmax_n(tmp, sf, 3);
        s_a[0] = sf[0]; s_a[1] = sf[1]; s_a[2] = sf[2];
    }
    __syncthreads();

    const float a0 = s_a[0], a1 = s_a[1], a2 = s_a[2];
    const float* r0 = emb + (size_t)question[b*3 + 0] * EMB_DIM;
    const float* r1 = emb + (size_t)question[b*3 + 1] * EMB_DIM;
    const float* r2 = emb + (size_t)question[b*3 + 2] * EMB_DIM;

    if (tid < 32) {
        const int o = og*32 + tid;
        s_cb[tid] = a0*r0[OFF_CNNB + o] + a1*r1[OFF_CNNB + o] + a2*r2[OFF_CNNB + o];
    }
    // zero padded stage once; halo stays zero across channel chunks
    for (int e = tid; e < 5184; e += 128) s_pad[e] = 0.f;
    __syncthreads();

    const int px  = tid & 31;
    const int wq  = tid >> 5;          // warp -> oc block of 8
    const int ocb = wq * 8;            // og-local oc base (even)
    const int h0  = px >> 4;           // 0/1 -> h block 8*h0..8*h0+7
    const int wi  = px & 15;

    ull_t acc2[4][8];                  // [oc-pair][h index r]
    #pragma unroll
    for (int i = 0; i < 4; i++)
        #pragma unroll
        for (int r = 0; r < 8; r++) acc2[i][r] = 0ULL;

    const float4* ci4 = (const float4*)(g_ci + (size_t)b * DIMC * HW);
    const int wgoff = og * 32 * 576;   // weight offset for this og (OFF_CNNW = 0)

    for (int cc = 0; cc < 4; ++cc) {
        // stage 16 channels of ci into TRANSPOSED padded smem [c][w+1][h+1]
        for (int e4 = tid; e4 < 1024; e4 += 128) {
            float4 v = ci4[cc*1024 + e4];
            const int e  = e4 * 4;
            const int cl = e >> 8;
            const int h  = (e >> 4) & 15;
            const int w  = e & 15;
            float* dstp = s_pad + cl*324 + (w + 1)*18 + (h + 1);
            dstp[0]  = v.x;            // w,   h
            dstp[18] = v.y;            // w+1, h
            dstp[36] = v.z;
            dstp[54] = v.w;
        }
        // stage this cc's weight slice: s_wc[klocal*34 + oc_local]
        for (int idx = tid; idx < 32*36; idx += 128) {
            const int oc_l = idx / 36;
            const int k4   = idx % 36;
            const int goff = wgoff + oc_l*576 + cc*144 + k4*4;
            float4 x = *(const float4*)(r0 + goff);
            float4 y = *(const float4*)(r1 + goff);
            float4 z = *(const float4*)(r2 + goff);
            float* w = s_wc + (k4*4)*CW_STRIDE + oc_l;
            w[0]           = a0*x.x + a1*y.x + a2*z.x;
            w[CW_STRIDE]   = a0*x.y + a1*y.y + a2*z.y;
            w[2*CW_STRIDE] = a0*x.z + a1*y.z + a2*z.z;
            w[3*CW_STRIDE] = a0*x.w + a1*y.w + a2*z.w;
        }
        __syncthreads();

        #pragma unroll 1
        for (int cl = 0; cl < 16; ++cl) {
            const float* chb = s_pad + cl*324 + 8*h0;
            #pragma unroll
            for (int kx = 0; kx < 3; ++kx) {
                // strip: rows 8h0..8h0+9 at column wi+kx, as 5 aligned float2
                const float2* sp = (const float2*)(chb + (wi + kx)*18);
                float2 s2[5];
                #pragma unroll
                for (int r = 0; r < 5; r++) s2[r] = sp[r];    // LDS.64, 2-phase CF
                const float sv[10] = { s2[0].x, s2[0].y, s2[1].x, s2[1].y, s2[2].x,
                                       s2[2].y, s2[3].x, s2[3].y, s2[4].x, s2[4].y };
                #pragma unroll
                for (int ky = 0; ky < 3; ++ky) {
                    const int klocal = cl*9 + ky*3 + kx;
                    const ull_t* wp = (const ull_t*)(s_wc + klocal*CW_STRIDE + ocb);
                    ull_t w2[4];
                    #pragma unroll
                    for (int i = 0; i < 4; i++) w2[i] = wp[i];  // uniform LDS.64, no pack
                    #pragma unroll
                    for (int r = 0; r < 8; r++) {
                        ull_t bv;
                        PACKF2(bv, sv[r + ky], sv[r + ky]);     // dup pack (alu)
                        #pragma unroll
                        for (int i = 0; i < 4; i++)
                            FMAF2(acc2[i][r], w2[i], bv, acc2[i][r]);
                    }
                }
            }
        }
        __syncthreads();
    }

    float* dst = (mod == 0) ? g_h1 : (mod == 1) ? g_h2 : out_final;
    dst += (size_t)b * DIMC * HW;
    #pragma unroll
    for (int i = 0; i < 4; i++) {
        const int o0 = og*32 + ocb + 2*i;
        const float b0v = s_cb[ocb + 2*i];
        const float b1v = s_cb[ocb + 2*i + 1];
        #pragma unroll
        for (int r = 0; r < 8; r++) {
            float lo, hi;
            UNPACKF2(lo, hi, acc2[i][r]);
            const int pos = (8*h0 + r)*16 + wi;
            dst[o0*256 + pos]       = fmaxf(lo + b0v, 0.f);
            dst[(o0 + 1)*256 + pos] = fmaxf(hi + b1v, 0.f);
        }
    }
}

// =====================================================================
extern "C" void kernel_launch(void* const* d_in, const int* in_sizes, int n_in,
                              void* d_out, int out_size)
{
    const int*   question = (const int*)  d_in[0];
    const float* img      = (const float*)d_in[1];
    const float* emb      = (const float*)d_in[2];
    const float* alpha    = (const float*)d_in[3];
    const float* tau0     = (const float*)d_in[4];
    const float* tau1     = (const float*)d_in[5];
    float* out = (float*)d_out;

    const int p_smem = P_SMEM_FLOATS * 4;
    const int c_smem = C_SMEM_FLOATS * 4;
    cudaFuncSetAttribute(proj_kernel, cudaFuncAttributeMaxDynamicSharedMemorySize, p_smem);
    cudaFuncSetAttribute(conv_kernel, cudaFuncAttributeMaxDynamicSharedMemorySize, c_smem);

    for (int mod = 0; mod < 3; ++mod) {
        proj_kernel<<<BATCH, 256, p_smem>>>(question, img, emb, alpha, tau0, tau1, mod);
        conv_kernel<<<BATCH*2, 128, c_smem>>>(question, emb, alpha, out, mod);
    }
    (void)in_sizes; (void)n_in; (void)out_size;
}

// round 10
// speedup vs baseline: 1.8818x; 1.8818x over previous
#include <cuda_runtime.h>
#include <cuda_bf16.h>
#include <stdint.h>
#include <math.h>

// ---------------- problem constants ----------------
#define DIMC      64
#define HW        256          // 16x16
#define BATCH     256
#define EMB_DIM   45184
#define OFF_CNNW  0
#define OFF_CNNB  36864
#define OFF_PROJW 36928
#define OFF_PROJB 45120
#define BHW       (BATCH*DIMC*HW)   // 16 MB

typedef unsigned long long ull_t;

// packed f32x2 helpers (proj kernel)
#define PACKF2(out, lo, hi) \
    asm("mov.b64 %0, {%1, %2};" : "=l"(out) : "f"(lo), "f"(hi))
#define FMAF2(d, a, b, c) \
    asm("fma.rn.f32x2 %0, %1, %2, %3;" : "=l"(d) : "l"(a), "l"(b), "l"(c))

// scratch
__device__ float g_h1[BHW];
__device__ float g_h2[BHW];
__device__ float g_ci[BHW];
// combined conv weights, tap-major, split bf16: [b][tap][oc][cl]
__device__ __nv_bfloat16 g_wh[BATCH*9*64*64];
__device__ __nv_bfloat16 g_wl[BATCH*9*64*64];

__device__ __forceinline__ void softmax_n(const float* x, float* y, int n) {
    float m = x[0];
    for (int i = 1; i < n; i++) m = fmaxf(m, x[i]);
    float s = 0.f;
    for (int i = 0; i < n; i++) { y[i] = expf(x[i] - m); s += y[i]; }
    float inv = 1.f / s;
    for (int i = 0; i < n; i++) y[i] *= inv;
}

__device__ __forceinline__ uint32_t smem_to_u32(const void* p) {
    uint32_t a;
    asm("{ .reg .u64 t; cvta.to.shared.u64 t, %1; cvt.u32.u64 %0, t; }" : "=r"(a) : "l"(p));
    return a;
}

// ldmatrix x4 (sm_75+ baseline)
__device__ __forceinline__ void ldmx4(uint32_t* r, uint32_t addr) {
    asm volatile("ldmatrix.sync.aligned.m8n8.x4.shared.b16 {%0,%1,%2,%3}, [%4];"
        : "=r"(r[0]), "=r"(r[1]), "=r"(r[2]), "=r"(r[3]) : "r"(addr));
}
// bf16 HMMA (sm_80+ baseline)
__device__ __forceinline__ void mma16816(float* d, const uint32_t* a, const uint32_t* b) {
    asm volatile("mma.sync.aligned.m16n8k16.row.col.f32.bf16.bf16.f32 "
        "{%0,%1,%2,%3}, {%4,%5,%6,%7}, {%8,%9}, {%0,%1,%2,%3};"
        : "+f"(d[0]), "+f"(d[1]), "+f"(d[2]), "+f"(d[3])
        : "r"(a[0]), "r"(a[1]), "r"(a[2]), "r"(a[3]), "r"(b[0]), "r"(b[1]));
}

// =====================================================================
// Kernel P: per-batch projection, f32x2 (unchanged — proven).
// =====================================================================
#define P_SMEM_FLOATS (16384 + 64*68 + 64 + 16)

__global__ void __launch_bounds__(256, 2)
proj_kernel(const int* __restrict__ question,
            const float* __restrict__ img,
            const float* __restrict__ emb,
            const float* __restrict__ alpha,
            const float* __restrict__ tau0,
            const float* __restrict__ tau1,
            int mod)
{
    extern __shared__ float sm[];
    float* s_stage = sm;                   // 64*256
    float* s_wT    = sm + 16384;           // 64*68
    float* s_pb    = sm + 16384 + 4352;    // 64
    float* s_scal  = s_pb + 64;            // 9

    const int b   = blockIdx.x;
    const int tid = threadIdx.x;

    if (tid == 0) {
        float tmp[4], sf[4];
        for (int t = 0; t < 3; t++) tmp[t] = alpha[mod*3 + t];
        softmax_n(tmp, sf, 3);
        s_scal[0] = sf[0]; s_scal[1] = sf[1]; s_scal[2] = sf[2];
        const int n = mod + 2;
        for (int m = 0; m < n; m++) tmp[m] = tau0[mod*4 + m];
        softmax_n(tmp, sf, n);
        s_scal[3] = sf[1];
        s_scal[4] = (n > 2) ? sf[2] : 0.f;
        s_scal[5] = (n > 3) ? sf[3] : 0.f;
        for (int m = 0; m < n; m++) tmp[m] = tau1[mod*4 + m];
        softmax_n(tmp, sf, n);
        s_scal[6] = sf[1];
        s_scal[7] = (n > 2) ? sf[2] : 0.f;
        s_scal[8] = (n > 3) ? sf[3] : 0.f;
    }
    __syncthreads();

    const float a0 = s_scal[0], a1 = s_scal[1], a2 = s_scal[2];
    const float* r0 = emb + (size_t)question[b*3 + 0] * EMB_DIM;
    const float* r1 = emb + (size_t)question[b*3 + 1] * EMB_DIM;
    const float* r2 = emb + (size_t)question[b*3 + 2] * EMB_DIM;

    if (tid < 64)
        s_pb[tid] = a0*r0[OFF_PROJB + tid] + a1*r1[OFF_PROJB + tid] + a2*r2[OFF_PROJB + tid];

    const int px = tid & 31;
    const int c0 = (tid >> 5) * 8;
    ull_t acc2[8][4];

    const float4* img4 = (const float4*)(img  + (size_t)b * DIMC * HW);
    const float4* h14  = (const float4*)(g_h1 + (size_t)b * DIMC * HW);
    const float4* h24  = (const float4*)(g_h2 + (size_t)b * DIMC * HW);
    float4* stage4 = (float4*)s_stage;

    for (int half = 0; half < 2; ++half) {
        const float w1 = s_scal[3 + 3*half + 0];
        const float w2 = s_scal[3 + 3*half + 1];
        const float w3 = s_scal[3 + 3*half + 2];

        for (int e4 = tid; e4 < 4096; e4 += 256) {
            float4 v = img4[e4];
            float4 o;
            o.x = w1*v.x; o.y = w1*v.y; o.z = w1*v.z; o.w = w1*v.w;
            if (mod >= 1) { float4 u = h14[e4]; o.x += w2*u.x; o.y += w2*u.y; o.z += w2*u.z; o.w += w2*u.w; }
            if (mod >= 2) { float4 u = h24[e4]; o.x += w3*u.x; o.y += w3*u.y; o.z += w3*u.z; o.w += w3*u.w; }
            stage4[e4] = o;
        }
        for (int e = tid; e < 4096; e += 256) {
            const int c  = e >> 6;
            const int kk = e & 63;
            const int off = OFF_PROJW + c*128 + half*64 + kk;
            s_wT[kk*68 + c] = a0*r0[off] + a1*r1[off] + a2*r2[off];
        }
        __syncthreads();

        if (half == 0) {
            #pragma unroll
            for (int ii = 0; ii < 8; ii++) {
                ull_t pbp;
                PACKF2(pbp, s_pb[c0 + ii], s_pb[c0 + ii]);
                #pragma unroll
                for (int j2 = 0; j2 < 4; j2++) acc2[ii][j2] = pbp;
            }
        }

        #pragma unroll 2
        for (int k = 0; k < 64; k++) {
            ull_t a2r[8];
            #pragma unroll
            for (int ii = 0; ii < 8; ii++) {
                const float wv = s_wT[k*68 + c0 + ii];
                PACKF2(a2r[ii], wv, wv);
            }
            ull_t b2[4];
            #pragma unroll
            for (int j2 = 0; j2 < 4; j2++)
                b2[j2] = *(const ull_t*)(s_stage + k*256 + 2*px + 64*j2);
            #pragma unroll
            for (int j2 = 0; j2 < 4; j2++)
                #pragma unroll
                for (int ii = 0; ii < 8; ii++)
                    FMAF2(acc2[ii][j2], a2r[ii], b2[j2], acc2[ii][j2]);
        }
        __syncthreads();
    }

    float* ci = g_ci + (size_t)b * DIMC * HW;
    #pragma unroll
    for (int ii = 0; ii < 8; ii++)
        #pragma unroll
        for (int j2 = 0; j2 < 4; j2++)
            *(ull_t*)(ci + (c0 + ii)*256 + 2*px + 64*j2) = acc2[ii][j2];
}

// =====================================================================
// Kernel W: combine conv weights, transpose tap-major, split bf16 hi/lo.
// =====================================================================
__global__ void __launch_bounds__(128)
wcomb_kernel(const int* __restrict__ question,
             const float* __restrict__ emb,
             const float* __restrict__ alpha,
             int mod)
{
    __shared__ float ws[16*580];
    __shared__ float s_a[3];
    const int b   = blockIdx.x;
    const int tid = threadIdx.x;

    if (tid == 0) {
        float tmp[3], sf[3];
        for (int t = 0; t < 3; t++) tmp[t] = alpha[mod*3 + t];
        softmax_n(tmp, sf, 3);
        s_a[0] = sf[0]; s_a[1] = sf[1]; s_a[2] = sf[2];
    }
    __syncthreads();
    const float a0 = s_a[0], a1 = s_a[1], a2 = s_a[2];
    const float* r0 = emb + (size_t)question[b*3 + 0] * EMB_DIM;
    const float* r1 = emb + (size_t)question[b*3 + 1] * EMB_DIM;
    const float* r2 = emb + (size_t)question[b*3 + 2] * EMB_DIM;
    const size_t obase = (size_t)b * 9 * 4096;

    for (int chunk = 0; chunk < 4; ++chunk) {
        const int oc0 = chunk * 16;
        for (int i4 = tid; i4 < 16*144; i4 += 128) {
            const int oc_l = i4 / 144;
            const int c4   = i4 % 144;
            const int f = (oc0 + oc_l)*576 + c4*4;
            float4 x = *(const float4*)(r0 + f);
            float4 y = *(const float4*)(r1 + f);
            float4 z = *(const float4*)(r2 + f);
            float4 o;
            o.x = a0*x.x + a1*y.x + a2*z.x;
            o.y = a0*x.y + a1*y.y + a2*z.y;
            o.z = a0*x.z + a1*y.z + a2*z.z;
            o.w = a0*x.w + a1*y.w + a2*z.w;
            *(float4*)&ws[oc_l*580 + c4*4] = o;
        }
        __syncthreads();
        for (int tap = 0; tap < 9; ++tap) {
            for (int e2 = tid; e2 < 512; e2 += 128) {
                const int oc_l = e2 >> 5;
                const int cl   = (e2 & 31) * 2;
                const float w0 = ws[oc_l*580 + cl*9 + tap];
                const float w1 = ws[oc_l*580 + (cl + 1)*9 + tap];
                __nv_bfloat16 h0 = __float2bfloat16(w0);
                __nv_bfloat16 h1 = __float2bfloat16(w1);
                __nv_bfloat16 l0 = __float2bfloat16(w0 - __bfloat162float(h0));
                __nv_bfloat16 l1 = __float2bfloat16(w1 - __bfloat162float(h1));
                const size_t idx = obase + (size_t)tap*4096 + (oc0 + oc_l)*64 + cl;
                __nv_bfloat162 hp; hp.x = h0; hp.y = h1;
                __nv_bfloat162 lp; lp.x = l0; lp.y = l1;
                *(__nv_bfloat162*)&g_wh[idx] = hp;
                *(__nv_bfloat162*)&g_wl[idx] = lp;
            }
        }
        __syncthreads();
    }
}

// =====================================================================
// Kernel C (HMMA): per-batch 3x3 conv via mma.sync.m16n8k16.bf16 split.
// grid 256 (1 CTA/batch), 256 thr (8 warps), 2 CTAs/SM.
// ci staged bf16 hi/lo [18][18] pixels x 64ch, pitch 144B (CF ldmatrix).
// Weights per tap [oc][cl] pitch 144B. im2col = address offset (dy,dx).
// Warp w: positions 32w..32w+31 (h in {2w,2w+1}), all 64 oc.
// =====================================================================
#define CPITCH 144
#define DPITCH 1072                       // 268 floats, 16B-aligned
#define SMB_H   0                         // 64*144 = 9216
#define SMB_L   9216
#define SM_BIAS 18432                     // 64 floats
#define SM_SCAL 18688                     // 3 floats (pad 16)
#define SM_CI_H 18704                     // 324 pixels * 144 = 46656
#define SM_CI_L (SM_CI_H + 46656)
#define SM_TOT  (SM_CI_L + 46656)         // 112016
#define SM_DST  SM_CI_H                   // reuse: 64*1072 = 68608 <= 93312

__global__ void __launch_bounds__(256, 2)
convm_kernel(const int* __restrict__ question,
             const float* __restrict__ emb,
             const float* __restrict__ alpha,
             float* __restrict__ out_final,
             int mod)
{
    extern __shared__ char smem[];
    const uint32_t sb = smem_to_u32(smem);
    const int b    = blockIdx.x;
    const int tid  = threadIdx.x;
    const int warp = tid >> 5;
    const int lane = tid & 31;
    float* s_scal = (float*)(smem + SM_SCAL);
    float* s_bias = (float*)(smem + SM_BIAS);

    if (tid == 0) {
        float tmp[3], sf[3];
        for (int t = 0; t < 3; t++) tmp[t] = alpha[mod*3 + t];
        softmax_n(tmp, sf, 3);
        s_scal[0] = sf[0]; s_scal[1] = sf[1]; s_scal[2] = sf[2];
    }
    // zero both ci stages (halo stays zero; pads unread by ldmatrix)
    {
        float4 z4 = make_float4(0.f, 0.f, 0.f, 0.f);
        float4* zp = (float4*)(smem + SM_CI_H);
        for (int i = tid; i < (2*46656)/16; i += 256) zp[i] = z4;
    }
    __syncthreads();

    const float a0 = s_scal[0], a1 = s_scal[1], a2 = s_scal[2];
    const float* r0 = emb + (size_t)question[b*3 + 0] * EMB_DIM;
    const float* r1 = emb + (size_t)question[b*3 + 1] * EMB_DIM;
    const float* r2 = emb + (size_t)question[b*3 + 2] * EMB_DIM;
    if (tid < 64)
        s_bias[tid] = a0*r0[OFF_CNNB + tid] + a1*r1[OFF_CNNB + tid] + a2*r2[OFF_CNNB + tid];

    // fill ci interior: pixel (h+1, w+1), channels as bf16 hi/lo, pitch 144
    {
        const float* cib = g_ci + (size_t)b * DIMC * HW;
        for (int ii = tid; ii < 2048; ii += 256) {
            const int cp = ii >> 6;              // channel pair 0..31
            const int p4 = (ii & 63) * 4;        // position base (w multiple of 4)
            const int h  = p4 >> 4;
            const int w  = p4 & 15;
            float4 v0 = *(const float4*)(cib + (2*cp)*256 + p4);
            float4 v1 = *(const float4*)(cib + (2*cp + 1)*256 + p4);
            const float x0[4] = { v0.x, v0.y, v0.z, v0.w };
            const float x1[4] = { v1.x, v1.y, v1.z, v1.w };
            #pragma unroll
            for (int l = 0; l < 4; l++) {
                const int pix = (h + 1)*18 + (w + 1 + l);
                __nv_bfloat16 h0 = __float2bfloat16(x0[l]);
                __nv_bfloat16 h1 = __float2bfloat16(x1[l]);
                __nv_bfloat16 l0 = __float2bfloat16(x0[l] - __bfloat162float(h0));
                __nv_bfloat16 l1 = __float2bfloat16(x1[l] - __bfloat162float(h1));
                __nv_bfloat162 hp; hp.x = h0; hp.y = h1;
                __nv_bfloat162 lp; lp.x = l0; lp.y = l1;
                *(__nv_bfloat162*)(smem + SM_CI_H + pix*CPITCH + cp*4) = hp;
                *(__nv_bfloat162*)(smem + SM_CI_L + pix*CPITCH + cp*4) = lp;
            }
        }
    }

    // accumulators: [m-tile][n-tile][frag]
    float d[2][8][4];
    #pragma unroll
    for (int m = 0; m < 2; m++)
        #pragma unroll
        for (int n = 0; n < 8; n++)
            #pragma unroll
            for (int q = 0; q < 4; q++) d[m][n][q] = 0.f;

    // lane-dependent ldmatrix address pieces
    const int wl    = lane & 15;              // A: w coordinate of row
    const int kh16  = (lane >> 4) * 16;       // A: k-half byte offset
    const int oc_l  = ((lane >> 4) & 1)*8 + (lane & 7);   // B: oc row within 16
    const int koff  = ((lane >> 3) & 1) * 16;             // B: k-half byte offset
    const int h0_   = warp*2;                  // m-tile h values: h0_, h0_+1

    const char* wsrcH = (const char*)(g_wh + (size_t)b*9*4096);
    const char* wsrcL = (const char*)(g_wl + (size_t)b*9*4096);

    for (int tap = 0; tap < 9; ++tap) {
        const int dy = tap / 3;
        const int dx = tap % 3;
        __syncthreads();     // prev-tap B reads done (and first iter: ci ready)
        // stage this tap's weights [oc][cl] pitch 144, hi and lo
        for (int i = tid; i < 512; i += 256) {
            const int oc = i >> 3;
            const int q  = i & 7;
            *(float4*)(smem + SMB_H + oc*CPITCH + q*16) =
                *(const float4*)(wsrcH + (size_t)tap*8192 + oc*128 + q*16);
            *(float4*)(smem + SMB_L + oc*CPITCH + q*16) =
                *(const float4*)(wsrcL + (size_t)tap*8192 + oc*128 + q*16);
        }
        __syncthreads();

        #pragma unroll
        for (int k16 = 0; k16 < 4; ++k16) {
            const int kb = k16 * 32;          // byte offset of cl0 within row
            uint32_t ah[2][4], al[2][4];
            #pragma unroll
            for (int m = 0; m < 2; m++) {
                const uint32_t apix = (uint32_t)(((h0_ + m + dy)*18 + wl + dx)*CPITCH + kh16 + kb);
                ldmx4(ah[m], sb + SM_CI_H + apix);
                ldmx4(al[m], sb + SM_CI_L + apix);
            }
            #pragma unroll
            for (int nt2 = 0; nt2 < 4; ++nt2) {
                uint32_t bh[4], bl[4];
                const uint32_t boff = (uint32_t)((nt2*16 + oc_l)*CPITCH + kb + koff);
                ldmx4(bh, sb + SMB_H + boff);
                ldmx4(bl, sb + SMB_L + boff);
                #pragma unroll
                for (int m = 0; m < 2; m++) {
                    mma16816(d[m][2*nt2],     ah[m], bh);
                    mma16816(d[m][2*nt2],     al[m], bh);
                    mma16816(d[m][2*nt2],     ah[m], bl);
                    mma16816(d[m][2*nt2 + 1], ah[m], bh + 2);
                    mma16816(d[m][2*nt2 + 1], al[m], bh + 2);
                    mma16816(d[m][2*nt2 + 1], ah[m], bl + 2);
                }
            }
        }
    }
    __syncthreads();   // all smem reads done; reuse ci region as D stage

    // scatter D frags to smem [oc][pos] pitch 1072
    {
        const int g  = lane >> 2;
        const int tg = lane & 3;
        #pragma unroll
        for (int m = 0; m < 2; m++) {
            const int hh = h0_ + m;
            const int pos0 = hh*16 + g;
            const int pos1 = pos0 + 8;
            #pragma unroll
            for (int n = 0; n < 8; n++) {
                char* base = smem + SM_DST + (n*8 + 2*tg)*DPITCH;
                *(float*)(base + pos0*4)          = d[m][n][0];
                *(float*)(base + DPITCH + pos0*4) = d[m][n][1];
                *(float*)(base + pos1*4)          = d[m][n][2];
                *(float*)(base + DPITCH + pos1*4) = d[m][n][3];
            }
        }
    }
    __syncthreads();

    float* dst = (mod == 0) ? g_h1 : (mod == 1) ? g_h2 : out_final;
    dst += (size_t)b * DIMC * HW;
    for (int i = tid; i < 4096; i += 256) {
        const int oc = i >> 6;
        const int p4 = (i & 63) * 4;
        float4 v = *(const float4*)(smem + SM_DST + oc*DPITCH + p4*4);
        const float bb = s_bias[oc];
        v.x = fmaxf(v.x + bb, 0.f);
        v.y = fmaxf(v.y + bb, 0.f);
        v.z = fmaxf(v.z + bb, 0.f);
        v.w = fmaxf(v.w + bb, 0.f);
        *(float4*)(dst + oc*256 + p4) = v;
    }
}

// =====================================================================
extern "C" void kernel_launch(void* const* d_in, const int* in_sizes, int n_in,
                              void* d_out, int out_size)
{
    const int*   question = (const int*)  d_in[0];
    const float* img      = (const float*)d_in[1];
    const float* emb      = (const float*)d_in[2];
    const float* alpha    = (const float*)d_in[3];
    const float* tau0     = (const float*)d_in[4];
    const float* tau1     = (const float*)d_in[5];
    float* out = (float*)d_out;

    const int p_smem = P_SMEM_FLOATS * 4;
    cudaFuncSetAttribute(proj_kernel, cudaFuncAttributeMaxDynamicSharedMemorySize, p_smem);
    cudaFuncSetAttribute(convm_kernel, cudaFuncAttributeMaxDynamicSharedMemorySize, SM_TOT);

    for (int mod = 0; mod < 3; ++mod) {
        wcomb_kernel<<<BATCH, 128>>>(question, emb, alpha, mod);
        proj_kernel<<<BATCH, 256, p_smem>>>(question, img, emb, alpha, tau0, tau1, mod);
        convm_kernel<<<BATCH, 256, SM_TOT>>>(question, emb, alpha, out, mod);
    }
    (void)in_sizes; (void)n_in; (void)out_size;
}

// round 11
// speedup vs baseline: 2.0961x; 1.1139x over previous
#include <cuda_runtime.h>
#include <cuda_bf16.h>
#include <stdint.h>
#include <math.h>

// ---------------- problem constants ----------------
#define DIMC      64
#define HW        256          // 16x16
#define BATCH     256
#define EMB_DIM   45184
#define OFF_CNNW  0
#define OFF_CNNB  36864
#define OFF_PROJW 36928
#define OFF_PROJB 45120
#define BHW       (BATCH*DIMC*HW)   // 16 MB

typedef unsigned long long ull_t;

// packed f32x2 helpers (proj kernel)
#define PACKF2(out, lo, hi) \
    asm("mov.b64 %0, {%1, %2};" : "=l"(out) : "f"(lo), "f"(hi))
#define FMAF2(d, a, b, c) \
    asm("fma.rn.f32x2 %0, %1, %2, %3;" : "=l"(d) : "l"(a), "l"(b), "l"(c))

// scratch
__device__ float g_h1[BHW];
__device__ float g_h2[BHW];
__device__ float g_ci[BHW];
// combined conv weights, per mod, tap-major, split bf16: [mod][b][tap][oc][cl]
__device__ __nv_bfloat16 g_wh[3*BATCH*9*64*64];
__device__ __nv_bfloat16 g_wl[3*BATCH*9*64*64];

__device__ __forceinline__ void softmax_n(const float* x, float* y, int n) {
    float m = x[0];
    for (int i = 1; i < n; i++) m = fmaxf(m, x[i]);
    float s = 0.f;
    for (int i = 0; i < n; i++) { y[i] = expf(x[i] - m); s += y[i]; }
    float inv = 1.f / s;
    for (int i = 0; i < n; i++) y[i] *= inv;
}

__device__ __forceinline__ uint32_t smem_to_u32(const void* p) {
    uint32_t a;
    asm("{ .reg .u64 t; cvta.to.shared.u64 t, %1; cvt.u32.u64 %0, t; }" : "=r"(a) : "l"(p));
    return a;
}

// ldmatrix x4 (sm_75+ baseline)
__device__ __forceinline__ void ldmx4(uint32_t* r, uint32_t addr) {
    asm volatile("ldmatrix.sync.aligned.m8n8.x4.shared.b16 {%0,%1,%2,%3}, [%4];"
        : "=r"(r[0]), "=r"(r[1]), "=r"(r[2]), "=r"(r[3]) : "r"(addr));
}
// bf16 HMMA (sm_80+ baseline)
__device__ __forceinline__ void mma16816(float* d, const uint32_t* a, const uint32_t* b) {
    asm volatile("mma.sync.aligned.m16n8k16.row.col.f32.bf16.bf16.f32 "
        "{%0,%1,%2,%3}, {%4,%5,%6,%7}, {%8,%9}, {%0,%1,%2,%3};"
        : "+f"(d[0]), "+f"(d[1]), "+f"(d[2]), "+f"(d[3])
        : "r"(a[0]), "r"(a[1]), "r"(a[2]), "r"(a[3]), "r"(b[0]), "r"(b[1]));
}

// =====================================================================
// Kernel P: per-batch projection, f32x2 (unchanged — proven).
// =====================================================================
#define P_SMEM_FLOATS (16384 + 64*68 + 64 + 16)

__global__ void __launch_bounds__(256, 2)
proj_kernel(const int* __restrict__ question,
            const float* __restrict__ img,
            const float* __restrict__ emb,
            const float* __restrict__ alpha,
            const float* __restrict__ tau0,
            const float* __restrict__ tau1,
            int mod)
{
    extern __shared__ float sm[];
    float* s_stage = sm;                   // 64*256
    float* s_wT    = sm + 16384;           // 64*68
    float* s_pb    = sm + 16384 + 4352;    // 64
    float* s_scal  = s_pb + 64;            // 9

    const int b   = blockIdx.x;
    const int tid = threadIdx.x;

    if (tid == 0) {
        float tmp[4], sf[4];
        for (int t = 0; t < 3; t++) tmp[t] = alpha[mod*3 + t];
        softmax_n(tmp, sf, 3);
        s_scal[0] = sf[0]; s_scal[1] = sf[1]; s_scal[2] = sf[2];
        const int n = mod + 2;
        for (int m = 0; m < n; m++) tmp[m] = tau0[mod*4 + m];
        softmax_n(tmp, sf, n);
        s_scal[3] = sf[1];
        s_scal[4] = (n > 2) ? sf[2] : 0.f;
        s_scal[5] = (n > 3) ? sf[3] : 0.f;
        for (int m = 0; m < n; m++) tmp[m] = tau1[mod*4 + m];
        softmax_n(tmp, sf, n);
        s_scal[6] = sf[1];
        s_scal[7] = (n > 2) ? sf[2] : 0.f;
        s_scal[8] = (n > 3) ? sf[3] : 0.f;
    }
    __syncthreads();

    const float a0 = s_scal[0], a1 = s_scal[1], a2 = s_scal[2];
    const float* r0 = emb + (size_t)question[b*3 + 0] * EMB_DIM;
    const float* r1 = emb + (size_t)question[b*3 + 1] * EMB_DIM;
    const float* r2 = emb + (size_t)question[b*3 + 2] * EMB_DIM;

    if (tid < 64)
        s_pb[tid] = a0*r0[OFF_PROJB + tid] + a1*r1[OFF_PROJB + tid] + a2*r2[OFF_PROJB + tid];

    const int px = tid & 31;
    const int c0 = (tid >> 5) * 8;
    ull_t acc2[8][4];

    const float4* img4 = (const float4*)(img  + (size_t)b * DIMC * HW);
    const float4* h14  = (const float4*)(g_h1 + (size_t)b * DIMC * HW);
    const float4* h24  = (const float4*)(g_h2 + (size_t)b * DIMC * HW);
    float4* stage4 = (float4*)s_stage;

    for (int half = 0; half < 2; ++half) {
        const float w1 = s_scal[3 + 3*half + 0];
        const float w2 = s_scal[3 + 3*half + 1];
        const float w3 = s_scal[3 + 3*half + 2];

        for (int e4 = tid; e4 < 4096; e4 += 256) {
            float4 v = img4[e4];
            float4 o;
            o.x = w1*v.x; o.y = w1*v.y; o.z = w1*v.z; o.w = w1*v.w;
            if (mod >= 1) { float4 u = h14[e4]; o.x += w2*u.x; o.y += w2*u.y; o.z += w2*u.z; o.w += w2*u.w; }
            if (mod >= 2) { float4 u = h24[e4]; o.x += w3*u.x; o.y += w3*u.y; o.z += w3*u.z; o.w += w3*u.w; }
            stage4[e4] = o;
        }
        for (int e = tid; e < 4096; e += 256) {
            const int c  = e >> 6;
            const int kk = e & 63;
            const int off = OFF_PROJW + c*128 + half*64 + kk;
            s_wT[kk*68 + c] = a0*r0[off] + a1*r1[off] + a2*r2[off];
        }
        __syncthreads();

        if (half == 0) {
            #pragma unroll
            for (int ii = 0; ii < 8; ii++) {
                ull_t pbp;
                PACKF2(pbp, s_pb[c0 + ii], s_pb[c0 + ii]);
                #pragma unroll
                for (int j2 = 0; j2 < 4; j2++) acc2[ii][j2] = pbp;
            }
        }

        #pragma unroll 2
        for (int k = 0; k < 64; k++) {
            ull_t a2r[8];
            #pragma unroll
            for (int ii = 0; ii < 8; ii++) {
                const float wv = s_wT[k*68 + c0 + ii];
                PACKF2(a2r[ii], wv, wv);
            }
            ull_t b2[4];
            #pragma unroll
            for (int j2 = 0; j2 < 4; j2++)
                b2[j2] = *(const ull_t*)(s_stage + k*256 + 2*px + 64*j2);
            #pragma unroll
            for (int j2 = 0; j2 < 4; j2++)
                #pragma unroll
                for (int ii = 0; ii < 8; ii++)
                    FMAF2(acc2[ii][j2], a2r[ii], b2[j2], acc2[ii][j2]);
        }
        __syncthreads();
    }

    float* ci = g_ci + (size_t)b * DIMC * HW;
    #pragma unroll
    for (int ii = 0; ii < 8; ii++)
        #pragma unroll
        for (int j2 = 0; j2 < 4; j2++)
            *(ull_t*)(ci + (c0 + ii)*256 + 2*px + 64*j2) = acc2[ii][j2];
}

// =====================================================================
// Kernel W: combine conv weights for ALL modules, one launch.
// grid 3072 = 256 b x 3 mod x 4 oc-chunks, 128 thr.
// Each CTA: one 16-oc chunk -> tap-major split bf16 hi/lo in gmem.
// =====================================================================
__global__ void __launch_bounds__(128)
wcomb_all_kernel(const int* __restrict__ question,
                 const float* __restrict__ emb,
                 const float* __restrict__ alpha)
{
    __shared__ float ws[16*580];
    __shared__ float s_a[3];
    const int idx   = blockIdx.x;
    const int b     = idx / 12;
    const int r     = idx % 12;
    const int mod   = r >> 2;
    const int chunk = r & 3;
    const int tid   = threadIdx.x;

    if (tid == 0) {
        float tmp[3], sf[3];
        for (int t = 0; t < 3; t++) tmp[t] = alpha[mod*3 + t];
        softmax_n(tmp, sf, 3);
        s_a[0] = sf[0]; s_a[1] = sf[1]; s_a[2] = sf[2];
    }
    __syncthreads();
    const float a0 = s_a[0], a1 = s_a[1], a2 = s_a[2];
    const float* r0 = emb + (size_t)question[b*3 + 0] * EMB_DIM;
    const float* r1 = emb + (size_t)question[b*3 + 1] * EMB_DIM;
    const float* r2 = emb + (size_t)question[b*3 + 2] * EMB_DIM;
    const size_t obase = ((size_t)mod*BATCH + b) * 9 * 4096;
    const int oc0 = chunk * 16;

    // stage 16 oc rows of combined fp32 weights (coalesced float4)
    for (int i4 = tid; i4 < 16*144; i4 += 128) {
        const int oc_l = i4 / 144;
        const int c4   = i4 % 144;
        const int f = (oc0 + oc_l)*576 + c4*4;
        float4 x = *(const float4*)(r0 + f);
        float4 y = *(const float4*)(r1 + f);
        float4 z = *(const float4*)(r2 + f);
        float4 o;
        o.x = a0*x.x + a1*y.x + a2*z.x;
        o.y = a0*x.y + a1*y.y + a2*z.y;
        o.z = a0*x.z + a1*y.z + a2*z.z;
        o.w = a0*x.w + a1*y.w + a2*z.w;
        *(float4*)&ws[oc_l*580 + c4*4] = o;
    }
    __syncthreads();
    // transpose to tap-major, split, store (coalesced bf16x2 STG)
    for (int tap = 0; tap < 9; ++tap) {
        for (int e2 = tid; e2 < 512; e2 += 128) {
            const int oc_l = e2 >> 5;
            const int cl   = (e2 & 31) * 2;
            const float w0 = ws[oc_l*580 + cl*9 + tap];
            const float w1 = ws[oc_l*580 + (cl + 1)*9 + tap];
            __nv_bfloat16 h0 = __float2bfloat16(w0);
            __nv_bfloat16 h1 = __float2bfloat16(w1);
            __nv_bfloat16 l0 = __float2bfloat16(w0 - __bfloat162float(h0));
            __nv_bfloat16 l1 = __float2bfloat16(w1 - __bfloat162float(h1));
            const size_t gi = obase + (size_t)tap*4096 + (oc0 + oc_l)*64 + cl;
            __nv_bfloat162 hp; hp.x = h0; hp.y = h1;
            __nv_bfloat162 lp; lp.x = l0; lp.y = l1;
            *(__nv_bfloat162*)&g_wh[gi] = hp;
            *(__nv_bfloat162*)&g_wl[gi] = lp;
        }
    }
}

// =====================================================================
// Kernel C (HMMA): per-batch 3x3 conv via mma.sync.m16n8k16.bf16 split.
// grid 256 (1 CTA/batch), 256 thr (8 warps), 2 CTAs/SM.
// =====================================================================
#define CPITCH 144
#define DPITCH 1072                       // 268 floats, 16B-aligned
#define SMB_H   0                         // 64*144 = 9216
#define SMB_L   9216
#define SM_BIAS 18432                     // 64 floats
#define SM_SCAL 18688                     // 3 floats (pad 16)
#define SM_CI_H 18704                     // 324 pixels * 144 = 46656
#define SM_CI_L (SM_CI_H + 46656)
#define SM_TOT  (SM_CI_L + 46656)         // 112016
#define SM_DST  SM_CI_H                   // reuse: 64*1072 = 68608 <= 93312

__global__ void __launch_bounds__(256, 2)
convm_kernel(const int* __restrict__ question,
             const float* __restrict__ emb,
             const float* __restrict__ alpha,
             float* __restrict__ out_final,
             int mod)
{
    extern __shared__ char smem[];
    const uint32_t sb = smem_to_u32(smem);
    const int b    = blockIdx.x;
    const int tid  = threadIdx.x;
    const int warp = tid >> 5;
    const int lane = tid & 31;
    float* s_scal = (float*)(smem + SM_SCAL);
    float* s_bias = (float*)(smem + SM_BIAS);

    if (tid == 0) {
        float tmp[3], sf[3];
        for (int t = 0; t < 3; t++) tmp[t] = alpha[mod*3 + t];
        softmax_n(tmp, sf, 3);
        s_scal[0] = sf[0]; s_scal[1] = sf[1]; s_scal[2] = sf[2];
    }
    // zero both ci stages (halo stays zero; pads unread by ldmatrix)
    {
        float4 z4 = make_float4(0.f, 0.f, 0.f, 0.f);
        float4* zp = (float4*)(smem + SM_CI_H);
        for (int i = tid; i < (2*46656)/16; i += 256) zp[i] = z4;
    }
    __syncthreads();

    const float a0 = s_scal[0], a1 = s_scal[1], a2 = s_scal[2];
    const float* r0 = emb + (size_t)question[b*3 + 0] * EMB_DIM;
    const float* r1 = emb + (size_t)question[b*3 + 1] * EMB_DIM;
    const float* r2 = emb + (size_t)question[b*3 + 2] * EMB_DIM;
    if (tid < 64)
        s_bias[tid] = a0*r0[OFF_CNNB + tid] + a1*r1[OFF_CNNB + tid] + a2*r2[OFF_CNNB + tid];

    // fill ci interior: pixel (h+1, w+1), channels as bf16 hi/lo, pitch 144
    {
        const float* cib = g_ci + (size_t)b * DIMC * HW;
        for (int ii = tid; ii < 2048; ii += 256) {
            const int cp = ii >> 6;              // channel pair 0..31
            const int p4 = (ii & 63) * 4;        // position base (w multiple of 4)
            const int h  = p4 >> 4;
            const int w  = p4 & 15;
            float4 v0 = *(const float4*)(cib + (2*cp)*256 + p4);
            float4 v1 = *(const float4*)(cib + (2*cp + 1)*256 + p4);
            const float x0[4] = { v0.x, v0.y, v0.z, v0.w };
            const float x1[4] = { v1.x, v1.y, v1.z, v1.w };
            #pragma unroll
            for (int l = 0; l < 4; l++) {
                const int pix = (h + 1)*18 + (w + 1 + l);
                __nv_bfloat16 h0 = __float2bfloat16(x0[l]);
                __nv_bfloat16 h1 = __float2bfloat16(x1[l]);
                __nv_bfloat16 l0 = __float2bfloat16(x0[l] - __bfloat162float(h0));
                __nv_bfloat16 l1 = __float2bfloat16(x1[l] - __bfloat162float(h1));
                __nv_bfloat162 hp; hp.x = h0; hp.y = h1;
                __nv_bfloat162 lp; lp.x = l0; lp.y = l1;
                *(__nv_bfloat162*)(smem + SM_CI_H + pix*CPITCH + cp*4) = hp;
                *(__nv_bfloat162*)(smem + SM_CI_L + pix*CPITCH + cp*4) = lp;
            }
        }
    }

    // accumulators: [m-tile][n-tile][frag]
    float d[2][8][4];
    #pragma unroll
    for (int m = 0; m < 2; m++)
        #pragma unroll
        for (int n = 0; n < 8; n++)
            #pragma unroll
            for (int q = 0; q < 4; q++) d[m][n][q] = 0.f;

    // lane-dependent ldmatrix address pieces
    const int wl    = lane & 15;              // A: w coordinate of row
    const int kh16  = (lane >> 4) * 16;       // A: k-half byte offset
    const int oc_l  = ((lane >> 4) & 1)*8 + (lane & 7);   // B: oc row within 16
    const int koff  = ((lane >> 3) & 1) * 16;             // B: k-half byte offset
    const int h0_   = warp*2;                  // m-tile h values: h0_, h0_+1

    const char* wsrcH = (const char*)(g_wh + ((size_t)mod*BATCH + b)*9*4096);
    const char* wsrcL = (const char*)(g_wl + ((size_t)mod*BATCH + b)*9*4096);

    for (int tap = 0; tap < 9; ++tap) {
        const int dy = tap / 3;
        const int dx = tap % 3;
        __syncthreads();     // prev-tap B reads done (and first iter: ci ready)
        // stage this tap's weights [oc][cl] pitch 144, hi and lo
        for (int i = tid; i < 512; i += 256) {
            const int oc = i >> 3;
            const int q  = i & 7;
            *(float4*)(smem + SMB_H + oc*CPITCH + q*16) =
                *(const float4*)(wsrcH + (size_t)tap*8192 + oc*128 + q*16);
            *(float4*)(smem + SMB_L + oc*CPITCH + q*16) =
                *(const float4*)(wsrcL + (size_t)tap*8192 + oc*128 + q*16);
        }
        __syncthreads();

        #pragma unroll
        for (int k16 = 0; k16 < 4; ++k16) {
            const int kb = k16 * 32;          // byte offset of cl0 within row
            uint32_t ah[2][4], al[2][4];
            #pragma unroll
            for (int m = 0; m < 2; m++) {
                const uint32_t apix = (uint32_t)(((h0_ + m + dy)*18 + wl + dx)*CPITCH + kh16 + kb);
                ldmx4(ah[m], sb + SM_CI_H + apix);
                ldmx4(al[m], sb + SM_CI_L + apix);
            }
            #pragma unroll
            for (int nt2 = 0; nt2 < 4; ++nt2) {
                uint32_t bh[4], bl[4];
                const uint32_t boff = (uint32_t)((nt2*16 + oc_l)*CPITCH + kb + koff);
                ldmx4(bh, sb + SMB_H + boff);
                ldmx4(bl, sb + SMB_L + boff);
                #pragma unroll
                for (int m = 0; m < 2; m++) {
                    mma16816(d[m][2*nt2],     ah[m], bh);
                    mma16816(d[m][2*nt2],     al[m], bh);
                    mma16816(d[m][2*nt2],     ah[m], bl);
                    mma16816(d[m][2*nt2 + 1], ah[m], bh + 2);
                    mma16816(d[m][2*nt2 + 1], al[m], bh + 2);
                    mma16816(d[m][2*nt2 + 1], ah[m], bl + 2);
                }
            }
        }
    }
    __syncthreads();   // all smem reads done; reuse ci region as D stage

    // scatter D frags to smem [oc][pos] pitch 1072
    {
        const int g  = lane >> 2;
        const int tg = lane & 3;
        #pragma unroll
        for (int m = 0; m < 2; m++) {
            const int hh = h0_ + m;
            const int pos0 = hh*16 + g;
            const int pos1 = pos0 + 8;
            #pragma unroll
            for (int n = 0; n < 8; n++) {
                char* base = smem + SM_DST + (n*8 + 2*tg)*DPITCH;
                *(float*)(base + pos0*4)          = d[m][n][0];
                *(float*)(base + DPITCH + pos0*4) = d[m][n][1];
                *(float*)(base + pos1*4)          = d[m][n][2];
                *(float*)(base + DPITCH + pos1*4) = d[m][n][3];
            }
        }
    }
    __syncthreads();

    float* dst = (mod == 0) ? g_h1 : (mod == 1) ? g_h2 : out_final;
    dst += (size_t)b * DIMC * HW;
    for (int i = tid; i < 4096; i += 256) {
        const int oc = i >> 6;
        const int p4 = (i & 63) * 4;
        float4 v = *(const float4*)(smem + SM_DST + oc*DPITCH + p4*4);
        const float bb = s_bias[oc];
        v.x = fmaxf(v.x + bb, 0.f);
        v.y = fmaxf(v.y + bb, 0.f);
        v.z = fmaxf(v.z + bb, 0.f);
        v.w = fmaxf(v.w + bb, 0.f);
        *(float4*)(dst + oc*256 + p4) = v;
    }
}

// =====================================================================
extern "C" void kernel_launch(void* const* d_in, const int* in_sizes, int n_in,
                              void* d_out, int out_size)
{
    const int*   question = (const int*)  d_in[0];
    const float* img      = (const float*)d_in[1];
    const float* emb      = (const float*)d_in[2];
    const float* alpha    = (const float*)d_in[3];
    const float* tau0     = (const float*)d_in[4];
    const float* tau1     = (const float*)d_in[5];
    float* out = (float*)d_out;

    const int p_smem = P_SMEM_FLOATS * 4;
    cudaFuncSetAttribute(proj_kernel, cudaFuncAttributeMaxDynamicSharedMemorySize, p_smem);
    cudaFuncSetAttribute(convm_kernel, cudaFuncAttributeMaxDynamicSharedMemorySize, SM_TOT);

    // all modules' conv weights in one parallel launch (independent of h_prev)
    wcomb_all_kernel<<<BATCH*12, 128>>>(question, emb, alpha);

    for (int mod = 0; mod < 3; ++mod) {
        proj_kernel<<<BATCH, 256, p_smem>>>(question, img, emb, alpha, tau0, tau1, mod);
        convm_kernel<<<BATCH, 256, SM_TOT>>>(question, emb, alpha, out, mod);
    }
    (void)in_sizes; (void)n_in; (void)out_size;
}

// round 12
// speedup vs baseline: 2.1979x; 1.0485x over previous
#include <cuda_runtime.h>
#include <cuda_bf16.h>
#include <stdint.h>
#include <math.h>

// ---------------- problem constants ----------------
#define DIMC      64
#define HW        256          // 16x16
#define BATCH     256
#define EMB_DIM   45184
#define OFF_CNNW  0
#define OFF_CNNB  36864
#define OFF_PROJW 36928
#define OFF_PROJB 45120
#define BHW       (BATCH*DIMC*HW)   // 16 MB

typedef unsigned long long ull_t;

// scratch
__device__ float g_h1[BHW];
__device__ float g_h2[BHW];
// projected conv-input, bf16 split hi/lo, layout [b][pos][ch]
__device__ __nv_bfloat16 g_cih[BATCH*HW*DIMC];
__device__ __nv_bfloat16 g_cil[BATCH*HW*DIMC];
// combined conv weights, per mod, tap-major, split bf16: [mod][b][tap][oc][cl]
__device__ __nv_bfloat16 g_wh[3*BATCH*9*64*64];
__device__ __nv_bfloat16 g_wl[3*BATCH*9*64*64];

__device__ __forceinline__ void softmax_n(const float* x, float* y, int n) {
    float m = x[0];
    for (int i = 1; i < n; i++) m = fmaxf(m, x[i]);
    float s = 0.f;
    for (int i = 0; i < n; i++) { y[i] = expf(x[i] - m); s += y[i]; }
    float inv = 1.f / s;
    for (int i = 0; i < n; i++) y[i] *= inv;
}

__device__ __forceinline__ uint32_t smem_to_u32(const void* p) {
    uint32_t a;
    asm("{ .reg .u64 t; cvta.to.shared.u64 t, %1; cvt.u32.u64 %0, t; }" : "=r"(a) : "l"(p));
    return a;
}

// ldmatrix x4 (sm_75+ baseline)
__device__ __forceinline__ void ldmx4(uint32_t* r, uint32_t addr) {
    asm volatile("ldmatrix.sync.aligned.m8n8.x4.shared.b16 {%0,%1,%2,%3}, [%4];"
        : "=r"(r[0]), "=r"(r[1]), "=r"(r[2]), "=r"(r[3]) : "r"(addr));
}
// bf16 HMMA (sm_80+ baseline)
__device__ __forceinline__ void mma16816(float* d, const uint32_t* a, const uint32_t* b) {
    asm volatile("mma.sync.aligned.m16n8k16.row.col.f32.bf16.bf16.f32 "
        "{%0,%1,%2,%3}, {%4,%5,%6,%7}, {%8,%9}, {%0,%1,%2,%3};"
        : "+f"(d[0]), "+f"(d[1]), "+f"(d[2]), "+f"(d[3])
        : "r"(a[0]), "r"(a[1]), "r"(a[2]), "r"(a[3]), "r"(b[0]), "r"(b[1]));
}

__device__ __forceinline__ __nv_bfloat162 split_hi2(float x, float y) {
    __nv_bfloat162 r; r.x = __float2bfloat16(x); r.y = __float2bfloat16(y); return r;
}
__device__ __forceinline__ __nv_bfloat162 split_lo2(float x, float y,
                                                    __nv_bfloat162 h) {
    __nv_bfloat162 r;
    r.x = __float2bfloat16(x - __bfloat162float(h.x));
    r.y = __float2bfloat16(y - __bfloat162float(h.y));
    return r;
}

// =====================================================================
// Kernel W: combine conv weights for ALL modules, one launch.
// grid 3072 = 256 b x 3 mod x 4 oc-chunks, 128 thr.
// =====================================================================
__global__ void __launch_bounds__(128)
wcomb_all_kernel(const int* __restrict__ question,
                 const float* __restrict__ emb,
                 const float* __restrict__ alpha)
{
    __shared__ float ws[16*580];
    __shared__ float s_a[3];
    const int idx   = blockIdx.x;
    const int b     = idx / 12;
    const int r     = idx % 12;
    const int mod   = r >> 2;
    const int chunk = r & 3;
    const int tid   = threadIdx.x;

    if (tid == 0) {
        float tmp[3], sf[3];
        for (int t = 0; t < 3; t++) tmp[t] = alpha[mod*3 + t];
        softmax_n(tmp, sf, 3);
        s_a[0] = sf[0]; s_a[1] = sf[1]; s_a[2] = sf[2];
    }
    __syncthreads();
    const float a0 = s_a[0], a1 = s_a[1], a2 = s_a[2];
    const float* r0 = emb + (size_t)question[b*3 + 0] * EMB_DIM;
    const float* r1 = emb + (size_t)question[b*3 + 1] * EMB_DIM;
    const float* r2 = emb + (size_t)question[b*3 + 2] * EMB_DIM;
    const size_t obase = ((size_t)mod*BATCH + b) * 9 * 4096;
    const int oc0 = chunk * 16;

    for (int i4 = tid; i4 < 16*144; i4 += 128) {
        const int oc_l = i4 / 144;
        const int c4   = i4 % 144;
        const int f = (oc0 + oc_l)*576 + c4*4;
        float4 x = *(const float4*)(r0 + f);
        float4 y = *(const float4*)(r1 + f);
        float4 z = *(const float4*)(r2 + f);
        float4 o;
        o.x = a0*x.x + a1*y.x + a2*z.x;
        o.y = a0*x.y + a1*y.y + a2*z.y;
        o.z = a0*x.z + a1*y.z + a2*z.z;
        o.w = a0*x.w + a1*y.w + a2*z.w;
        *(float4*)&ws[oc_l*580 + c4*4] = o;
    }
    __syncthreads();
    for (int tap = 0; tap < 9; ++tap) {
        for (int e2 = tid; e2 < 512; e2 += 128) {
            const int oc_l = e2 >> 5;
            const int cl   = (e2 & 31) * 2;
            const float w0 = ws[oc_l*580 + cl*9 + tap];
            const float w1 = ws[oc_l*580 + (cl + 1)*9 + tap];
            __nv_bfloat162 hp = split_hi2(w0, w1);
            __nv_bfloat162 lp = split_lo2(w0, w1, hp);
            const size_t gi = obase + (size_t)tap*4096 + (oc0 + oc_l)*64 + cl;
            *(__nv_bfloat162*)&g_wh[gi] = hp;
            *(__nv_bfloat162*)&g_wl[gi] = lp;
        }
    }
}

// =====================================================================
// Kernel P (HMMA): per-batch projection via mma.sync bf16 split.
// grid 256 (1 CTA/batch), 256 thr (8 warps), 2 CTAs/SM.
// D[256 pos, 64 ch] = inp[256,128] @ W[128,64]^T + pb; 2 K-halves (lhs/rhs).
// A stage [pos][64ch] pitch 144 hi/lo; B stage [oc][64k] pitch 144 hi/lo.
// Epilogue: split to bf16 hi/lo and store g_cih/g_cil [b][pos][ch].
// =====================================================================
#define CPITCH 144
#define PJ_BH   0                         // 64*144 = 9216
#define PJ_BL   9216                      // -> 18432
#define PJ_PB   18432                     // 64 floats -> 18688
#define PJ_SC   18688                     // 9 scalars (pad 64) -> 18752
#define PJ_AH   18752                     // 256*144 = 36864 -> 55616
#define PJ_AL   55616                     // -> 92480
#define PJ_TOT  92480

__global__ void __launch_bounds__(256, 2)
projm_kernel(const int* __restrict__ question,
             const float* __restrict__ img,
             const float* __restrict__ emb,
             const float* __restrict__ alpha,
             const float* __restrict__ tau0,
             const float* __restrict__ tau1,
             int mod)
{
    extern __shared__ char smem[];
    const uint32_t sb = smem_to_u32(smem);
    const int b    = blockIdx.x;
    const int tid  = threadIdx.x;
    const int warp = tid >> 5;
    const int lane = tid & 31;
    float* s_pb   = (float*)(smem + PJ_PB);
    float* s_scal = (float*)(smem + PJ_SC);

    if (tid == 0) {
        float tmp[4], sf[4];
        for (int t = 0; t < 3; t++) tmp[t] = alpha[mod*3 + t];
        softmax_n(tmp, sf, 3);
        s_scal[0] = sf[0]; s_scal[1] = sf[1]; s_scal[2] = sf[2];
        const int n = mod + 2;
        for (int m = 0; m < n; m++) tmp[m] = tau0[mod*4 + m];
        softmax_n(tmp, sf, n);
        s_scal[3] = sf[1];
        s_scal[4] = (n > 2) ? sf[2] : 0.f;
        s_scal[5] = (n > 3) ? sf[3] : 0.f;
        for (int m = 0; m < n; m++) tmp[m] = tau1[mod*4 + m];
        softmax_n(tmp, sf, n);
        s_scal[6] = sf[1];
        s_scal[7] = (n > 2) ? sf[2] : 0.f;
        s_scal[8] = (n > 3) ? sf[3] : 0.f;
    }
    __syncthreads();

    const float a0 = s_scal[0], a1 = s_scal[1], a2 = s_scal[2];
    const float* r0 = emb + (size_t)question[b*3 + 0] * EMB_DIM;
    const float* r1 = emb + (size_t)question[b*3 + 1] * EMB_DIM;
    const float* r2 = emb + (size_t)question[b*3 + 2] * EMB_DIM;
    if (tid < 64)
        s_pb[tid] = a0*r0[OFF_PROJB + tid] + a1*r1[OFF_PROJB + tid] + a2*r2[OFF_PROJB + tid];

    // lane-dependent fragment address pieces (as convm)
    const int wl   = lane & 15;
    const int kh16 = (lane >> 4) * 16;
    const int oc_l = ((lane >> 4) & 1)*8 + (lane & 7);
    const int koff = ((lane >> 3) & 1) * 16;
    const int g    = lane >> 2;
    const int tg   = lane & 3;

    const float4* img4 = (const float4*)(img  + (size_t)b * DIMC * HW);
    const float4* h14  = (const float4*)(g_h1 + (size_t)b * DIMC * HW);
    const float4* h24  = (const float4*)(g_h2 + (size_t)b * DIMC * HW);

    // accumulators init with proj bias (col = n*8 + 2tg {,+1})
    float d[2][8][4];
    __syncthreads();   // s_pb ready
    #pragma unroll
    for (int n = 0; n < 8; n++) {
        const float p0 = s_pb[n*8 + 2*tg];
        const float p1 = s_pb[n*8 + 2*tg + 1];
        #pragma unroll
        for (int m = 0; m < 2; m++) {
            d[m][n][0] = p0; d[m][n][1] = p1;
            d[m][n][2] = p0; d[m][n][3] = p1;
        }
    }

    for (int half = 0; half < 2; ++half) {
        const float w1 = s_scal[3 + 3*half + 0];
        const float w2 = s_scal[3 + 3*half + 1];
        const float w3 = s_scal[3 + 3*half + 2];
        __syncthreads();   // prev half's smem reads done

        // A stage: inp-half [pos 256][ch 64] bf16 hi/lo, pitch 144
        for (int ii = tid; ii < 2048; ii += 256) {
            const int cp = ii >> 6;              // channel pair 0..31
            const int q  = ii & 63;              // pos4 group
            const int i0 = (2*cp)*64 + q;
            float4 u0 = img4[i0];
            float4 u1 = img4[i0 + 64];
            float4 o0, o1;
            o0.x = w1*u0.x; o0.y = w1*u0.y; o0.z = w1*u0.z; o0.w = w1*u0.w;
            o1.x = w1*u1.x; o1.y = w1*u1.y; o1.z = w1*u1.z; o1.w = w1*u1.w;
            if (mod >= 1) {
                float4 v0 = h14[i0], v1 = h14[i0 + 64];
                o0.x += w2*v0.x; o0.y += w2*v0.y; o0.z += w2*v0.z; o0.w += w2*v0.w;
                o1.x += w2*v1.x; o1.y += w2*v1.y; o1.z += w2*v1.z; o1.w += w2*v1.w;
            }
            if (mod >= 2) {
                float4 v0 = h24[i0], v1 = h24[i0 + 64];
                o0.x += w3*v0.x; o0.y += w3*v0.y; o0.z += w3*v0.z; o0.w += w3*v0.w;
                o1.x += w3*v1.x; o1.y += w3*v1.y; o1.z += w3*v1.z; o1.w += w3*v1.w;
            }
            const float x0[4] = { o0.x, o0.y, o0.z, o0.w };
            const float x1[4] = { o1.x, o1.y, o1.z, o1.w };
            const int p0 = q * 4;
            #pragma unroll
            for (int l = 0; l < 4; l++) {
                __nv_bfloat162 hp = split_hi2(x0[l], x1[l]);
                __nv_bfloat162 lp = split_lo2(x0[l], x1[l], hp);
                *(__nv_bfloat162*)(smem + PJ_AH + (p0 + l)*CPITCH + cp*4) = hp;
                *(__nv_bfloat162*)(smem + PJ_AL + (p0 + l)*CPITCH + cp*4) = lp;
            }
        }
        // B stage: W-half [oc 64][k 64] bf16 hi/lo, pitch 144
        for (int idx = tid; idx < 1024; idx += 256) {
            const int oc = idx >> 4;
            const int kk = (idx & 15) * 4;
            const int f = OFF_PROJW + oc*128 + half*64 + kk;
            float4 x = *(const float4*)(r0 + f);
            float4 y = *(const float4*)(r1 + f);
            float4 z = *(const float4*)(r2 + f);
            float4 o;
            o.x = a0*x.x + a1*y.x + a2*z.x;
            o.y = a0*x.y + a1*y.y + a2*z.y;
            o.z = a0*x.z + a1*y.z + a2*z.z;
            o.w = a0*x.w + a1*y.w + a2*z.w;
            __nv_bfloat162 hp0 = split_hi2(o.x, o.y);
            __nv_bfloat162 lp0 = split_lo2(o.x, o.y, hp0);
            __nv_bfloat162 hp1 = split_hi2(o.z, o.w);
            __nv_bfloat162 lp1 = split_lo2(o.z, o.w, hp1);
            char* bh = smem + PJ_BH + oc*CPITCH + kk*2;
            char* bl = smem + PJ_BL + oc*CPITCH + kk*2;
            *(__nv_bfloat162*)(bh)     = hp0;
            *(__nv_bfloat162*)(bh + 4) = hp1;
            *(__nv_bfloat162*)(bl)     = lp0;
            *(__nv_bfloat162*)(bl + 4) = lp1;
        }
        __syncthreads();

        #pragma unroll
        for (int k16 = 0; k16 < 4; ++k16) {
            const int kb = k16 * 32;
            uint32_t ah[2][4], al[2][4];
            #pragma unroll
            for (int m = 0; m < 2; m++) {
                const uint32_t apix = (uint32_t)((warp*32 + m*16 + wl)*CPITCH + kh16 + kb);
                ldmx4(ah[m], sb + PJ_AH + apix);
                ldmx4(al[m], sb + PJ_AL + apix);
            }
            #pragma unroll
            for (int nt2 = 0; nt2 < 4; ++nt2) {
                uint32_t bh[4], bl[4];
                const uint32_t boff = (uint32_t)((nt2*16 + oc_l)*CPITCH + kb + koff);
                ldmx4(bh, sb + PJ_BH + boff);
                ldmx4(bl, sb + PJ_BL + boff);
                #pragma unroll
                for (int m = 0; m < 2; m++) {
                    mma16816(d[m][2*nt2],     ah[m], bh);
                    mma16816(d[m][2*nt2],     al[m], bh);
                    mma16816(d[m][2*nt2],     ah[m], bl);
                    mma16816(d[m][2*nt2 + 1], ah[m], bh + 2);
                    mma16816(d[m][2*nt2 + 1], al[m], bh + 2);
                    mma16816(d[m][2*nt2 + 1], ah[m], bl + 2);
                }
            }
        }
    }

    // epilogue: split to bf16 hi/lo -> g_cih/g_cil [b][pos][ch]
    __nv_bfloat16* cih = g_cih + (size_t)b * HW * DIMC;
    __nv_bfloat16* cil = g_cil + (size_t)b * HW * DIMC;
    #pragma unroll
    for (int m = 0; m < 2; m++) {
        const int row0 = warp*32 + m*16 + g;
        #pragma unroll
        for (int n = 0; n < 8; n++) {
            const int col = n*8 + 2*tg;
            __nv_bfloat162 h0 = split_hi2(d[m][n][0], d[m][n][1]);
            __nv_bfloat162 l0 = split_lo2(d[m][n][0], d[m][n][1], h0);
            __nv_bfloat162 h1 = split_hi2(d[m][n][2], d[m][n][3]);
            __nv_bfloat162 l1 = split_lo2(d[m][n][2], d[m][n][3], h1);
            *(__nv_bfloat162*)(cih + row0*64 + col)       = h0;
            *(__nv_bfloat162*)(cil + row0*64 + col)       = l0;
            *(__nv_bfloat162*)(cih + (row0 + 8)*64 + col) = h1;
            *(__nv_bfloat162*)(cil + (row0 + 8)*64 + col) = l1;
        }
    }
}

// =====================================================================
// Kernel C (HMMA): per-batch 3x3 conv via mma.sync.m16n8k16.bf16 split.
// grid 256 (1 CTA/batch), 256 thr (8 warps), 2 CTAs/SM.
// ci now arrives pre-split bf16 [b][pos][ch] -> fill is a pure row copy.
// =====================================================================
#define DPITCH 1072                       // 268 floats, 16B-aligned
#define SMB_H   0                         // 64*144 = 9216
#define SMB_L   9216
#define SM_BIAS 18432                     // 64 floats
#define SM_SCAL 18688                     // 3 floats (pad 16)
#define SM_CI_H 18704                     // 324 pixels * 144 = 46656
#define SM_CI_L (SM_CI_H + 46656)
#define SM_TOT  (SM_CI_L + 46656)         // 112016
#define SM_DST  SM_CI_H                   // reuse: 64*1072 = 68608 <= 93312

__global__ void __launch_bounds__(256, 2)
convm_kernel(const int* __restrict__ question,
             const float* __restrict__ emb,
             const float* __restrict__ alpha,
             float* __restrict__ out_final,
             int mod)
{
    extern __shared__ char smem[];
    const uint32_t sb = smem_to_u32(smem);
    const int b    = blockIdx.x;
    const int tid  = threadIdx.x;
    const int warp = tid >> 5;
    const int lane = tid & 31;
    float* s_scal = (float*)(smem + SM_SCAL);
    float* s_bias = (float*)(smem + SM_BIAS);

    if (tid == 0) {
        float tmp[3], sf[3];
        for (int t = 0; t < 3; t++) tmp[t] = alpha[mod*3 + t];
        softmax_n(tmp, sf, 3);
        s_scal[0] = sf[0]; s_scal[1] = sf[1]; s_scal[2] = sf[2];
    }
    // zero both ci stages (halo stays zero; pads unread by ldmatrix)
    {
        float4 z4 = make_float4(0.f, 0.f, 0.f, 0.f);
        float4* zp = (float4*)(smem + SM_CI_H);
        for (int i = tid; i < (2*46656)/16; i += 256) zp[i] = z4;
    }
    __syncthreads();

    const float a0 = s_scal[0], a1 = s_scal[1], a2 = s_scal[2];
    const float* r0 = emb + (size_t)question[b*3 + 0] * EMB_DIM;
    const float* r1 = emb + (size_t)question[b*3 + 1] * EMB_DIM;
    const float* r2 = emb + (size_t)question[b*3 + 2] * EMB_DIM;
    if (tid < 64)
        s_bias[tid] = a0*r0[OFF_CNNB + tid] + a1*r1[OFF_CNNB + tid] + a2*r2[OFF_CNNB + tid];

    // fill ci interior: pure 128B row copies from pre-split gmem
    {
        const char* cih = (const char*)(g_cih + (size_t)b * HW * DIMC);
        const char* cil = (const char*)(g_cil + (size_t)b * HW * DIMC);
        for (int i = tid; i < 2048; i += 256) {
            const int pos = i >> 3;
            const int q   = (i & 7) * 16;
            const int h   = pos >> 4;
            const int w   = pos & 15;
            const int pix = (h + 1)*18 + (w + 1);
            *(float4*)(smem + SM_CI_H + pix*CPITCH + q) = *(const float4*)(cih + pos*128 + q);
            *(float4*)(smem + SM_CI_L + pix*CPITCH + q) = *(const float4*)(cil + pos*128 + q);
        }
    }

    // accumulators: [m-tile][n-tile][frag]
    float d[2][8][4];
    #pragma unroll
    for (int m = 0; m < 2; m++)
        #pragma unroll
        for (int n = 0; n < 8; n++)
            #pragma unroll
            for (int q = 0; q < 4; q++) d[m][n][q] = 0.f;

    // lane-dependent ldmatrix address pieces
    const int wl    = lane & 15;
    const int kh16  = (lane >> 4) * 16;
    const int oc_l  = ((lane >> 4) & 1)*8 + (lane & 7);
    const int koff  = ((lane >> 3) & 1) * 16;
    const int h0_   = warp*2;

    const char* wsrcH = (const char*)(g_wh + ((size_t)mod*BATCH + b)*9*4096);
    const char* wsrcL = (const char*)(g_wl + ((size_t)mod*BATCH + b)*9*4096);

    for (int tap = 0; tap < 9; ++tap) {
        const int dy = tap / 3;
        const int dx = tap % 3;
        __syncthreads();     // prev-tap B reads done (and first iter: ci ready)
        for (int i = tid; i < 512; i += 256) {
            const int oc = i >> 3;
            const int q  = i & 7;
            *(float4*)(smem + SMB_H + oc*CPITCH + q*16) =
                *(const float4*)(wsrcH + (size_t)tap*8192 + oc*128 + q*16);
            *(float4*)(smem + SMB_L + oc*CPITCH + q*16) =
                *(const float4*)(wsrcL + (size_t)tap*8192 + oc*128 + q*16);
        }
        __syncthreads();

        #pragma unroll
        for (int k16 = 0; k16 < 4; ++k16) {
            const int kb = k16 * 32;
            uint32_t ah[2][4], al[2][4];
            #pragma unroll
            for (int m = 0; m < 2; m++) {
                const uint32_t apix = (uint32_t)(((h0_ + m + dy)*18 + wl + dx)*CPITCH + kh16 + kb);
                ldmx4(ah[m], sb + SM_CI_H + apix);
                ldmx4(al[m], sb + SM_CI_L + apix);
            }
            #pragma unroll
            for (int nt2 = 0; nt2 < 4; ++nt2) {
                uint32_t bh[4], bl[4];
                const uint32_t boff = (uint32_t)((nt2*16 + oc_l)*CPITCH + kb + koff);
                ldmx4(bh, sb + SMB_H + boff);
                ldmx4(bl, sb + SMB_L + boff);
                #pragma unroll
                for (int m = 0; m < 2; m++) {
                    mma16816(d[m][2*nt2],     ah[m], bh);
                    mma16816(d[m][2*nt2],     al[m], bh);
                    mma16816(d[m][2*nt2],     ah[m], bl);
                    mma16816(d[m][2*nt2 + 1], ah[m], bh + 2);
                    mma16816(d[m][2*nt2 + 1], al[m], bh + 2);
                    mma16816(d[m][2*nt2 + 1], ah[m], bl + 2);
                }
            }
        }
    }
    __syncthreads();   // all smem reads done; reuse ci region as D stage

    // scatter D frags to smem [oc][pos] pitch 1072
    {
        const int g  = lane >> 2;
        const int tg = lane & 3;
        #pragma unroll
        for (int m = 0; m < 2; m++) {
            const int hh = h0_ + m;
            const int pos0 = hh*16 + g;
            const int pos1 = pos0 + 8;
            #pragma unroll
            for (int n = 0; n < 8; n++) {
                char* base = smem + SM_DST + (n*8 + 2*tg)*DPITCH;
                *(float*)(base + pos0*4)          = d[m][n][0];
                *(float*)(base + DPITCH + pos0*4) = d[m][n][1];
                *(float*)(base + pos1*4)          = d[m][n][2];
                *(float*)(base + DPITCH + pos1*4) = d[m][n][3];
            }
        }
    }
    __syncthreads();

    float* dst = (mod == 0) ? g_h1 : (mod == 1) ? g_h2 : out_final;
    dst += (size_t)b * DIMC * HW;
    for (int i = tid; i < 4096; i += 256) {
        const int oc = i >> 6;
        const int p4 = (i & 63) * 4;
        float4 v = *(const float4*)(smem + SM_DST + oc*DPITCH + p4*4);
        const float bb = s_bias[oc];
        v.x = fmaxf(v.x + bb, 0.f);
        v.y = fmaxf(v.y + bb, 0.f);
        v.z = fmaxf(v.z + bb, 0.f);
        v.w = fmaxf(v.w + bb, 0.f);
        *(float4*)(dst + oc*256 + p4) = v;
    }
}

// =====================================================================
extern "C" void kernel_launch(void* const* d_in, const int* in_sizes, int n_in,
                              void* d_out, int out_size)
{
    const int*   question = (const int*)  d_in[0];
    const float* img      = (const float*)d_in[1];
    const float* emb      = (const float*)d_in[2];
    const float* alpha    = (const float*)d_in[3];
    const float* tau0     = (const float*)d_in[4];
    const float* tau1     = (const float*)d_in[5];
    float* out = (float*)d_out;

    cudaFuncSetAttribute(projm_kernel, cudaFuncAttributeMaxDynamicSharedMemorySize, PJ_TOT);
    cudaFuncSetAttribute(convm_kernel, cudaFuncAttributeMaxDynamicSharedMemorySize, SM_TOT);

    // all modules' conv weights in one parallel launch (independent of h_prev)
    wcomb_all_kernel<<<BATCH*12, 128>>>(question, emb, alpha);

    for (int mod = 0; mod < 3; ++mod) {
        projm_kernel<<<BATCH, 256, PJ_TOT>>>(question, img, emb, alpha, tau0, tau1, mod);
        convm_kernel<<<BATCH, 256, SM_TOT>>>(question, emb, alpha, out, mod);
    }
    (void)in_sizes; (void)n_in; (void)out_size;
}